// round 7
// baseline (speedup 1.0000x reference)
#include <cuda_runtime.h>
#include <cuda_bf16.h>
#include <cstdint>
#include <math.h>

#define B 4
#define C 64
#define N 4096

// ---------------------------------------------------------------------------
// Scratch (device globals, allocation-free rule)
// ---------------------------------------------------------------------------
__device__ __align__(16) __nv_bfloat16 g_Qb[B * N * 8];   // [b][n][8], scaled 0.125*log2e
__device__ __align__(16) __nv_bfloat16 g_Kb[B * N * 8];   // [b][m][8]
__device__ __align__(16) __nv_bfloat16 g_Vt[B * C * N];   // [b][ch][m] transposed
__device__ float g_gate[B * C];
__device__ float g_part[B * 64 * C];                       // per-CTA channel sums

// ---------------------------------------------------------------------------
// Helpers
// ---------------------------------------------------------------------------
__device__ __forceinline__ uint32_t smem_u32(const void* p) {
    uint32_t a;
    asm("{ .reg .u64 t; cvta.to.shared.u64 t, %1; cvt.u32.u64 %0, t; }" : "=r"(a) : "l"(p));
    return a;
}
__device__ __forceinline__ float ex2f(float x) {
    float r;
    asm("ex2.approx.ftz.f32 %0, %1;" : "=f"(r) : "f"(x));
    return r;
}
#define CVT2(r, a, b) \
    asm("cvt.rn.satfinite.bf16x2.f32 %0, %1, %2;" : "=r"(r) : "f"(b), "f"(a))
#define CP_ASYNC16(dst, src) \
    asm volatile("cp.async.cg.shared.global [%0], [%1], 16;" :: "r"(dst), "l"(src) : "memory")
#define CP_COMMIT() asm volatile("cp.async.commit_group;" ::: "memory")
#define CP_WAIT0()  asm volatile("cp.async.wait_group 0;" ::: "memory")

#define LDSM_X2(r0, r1, a) \
    asm volatile("ldmatrix.sync.aligned.m8n8.x2.shared.b16 {%0,%1}, [%2];" \
                 : "=r"(r0), "=r"(r1) : "r"(a))
#define LDSM_X4(r0, r1, r2, r3, a) \
    asm volatile("ldmatrix.sync.aligned.m8n8.x4.shared.b16 {%0,%1,%2,%3}, [%4];" \
                 : "=r"(r0), "=r"(r1), "=r"(r2), "=r"(r3) : "r"(a))

__device__ __forceinline__ void mma_k8(float& c0, float& c1, float& c2, float& c3,
                                       uint32_t a0, uint32_t a1, uint32_t b0) {
    asm volatile(
        "mma.sync.aligned.m16n8k8.row.col.f32.bf16.bf16.f32 "
        "{%0,%1,%2,%3}, {%4,%5}, {%6}, {%0,%1,%2,%3};"
        : "+f"(c0), "+f"(c1), "+f"(c2), "+f"(c3)
        : "r"(a0), "r"(a1), "r"(b0));
}
__device__ __forceinline__ void mma_k16(float* c, const uint32_t* a,
                                        uint32_t b0, uint32_t b1) {
    asm volatile(
        "mma.sync.aligned.m16n8k16.row.col.f32.bf16.bf16.f32 "
        "{%0,%1,%2,%3}, {%4,%5,%6,%7}, {%8,%9}, {%0,%1,%2,%3};"
        : "+f"(c[0]), "+f"(c[1]), "+f"(c[2]), "+f"(c[3])
        : "r"(a[0]), "r"(a[1]), "r"(a[2]), "r"(a[3]), "r"(b0), "r"(b1));
}

// exp(s/8) = 2^(s * 0.125*log2e); scale folded into Q
#define QSCALE (0.125f * 1.4426950408889634f)

// ---------------------------------------------------------------------------
// Kernel 1: QKV projections + SE partial channel sums.
// 256 CTAs x 256 thr, 64 pixels/CTA, 4 threads/pixel (20 outputs each).
// ---------------------------------------------------------------------------
#define XPITCH 68   // floats per sX row (64 px + 4 pad): kills SE bank conflicts

__global__ void __launch_bounds__(256) qkv_kernel(
    const float* __restrict__ x,
    const float* __restrict__ Wq, const float* __restrict__ bq,
    const float* __restrict__ Wk, const float* __restrict__ bk,
    const float* __restrict__ Wv, const float* __restrict__ bv) {
    __shared__ float sX[C * XPITCH];             // 17408 B
    __shared__ float4 sWq4[8 * 16], sWk4[8 * 16], sWv4[C * 16];
    __shared__ float sbq[8], sbk[8], sbv[C];
    __shared__ float spart[256];

    int t = threadIdx.x;
    {
        const float4* Wq4 = (const float4*)Wq;
        const float4* Wk4 = (const float4*)Wk;
        const float4* Wv4 = (const float4*)Wv;
        if (t < 128) { sWq4[t] = Wq4[t]; sWk4[t] = Wk4[t]; }
        for (int i = t; i < C * 16; i += 256) sWv4[i] = Wv4[i];
        if (t < 8) { sbq[t] = bq[t]; sbk[t] = bk[t]; }
        if (t < C) sbv[t] = bv[t];
    }

    int pix0 = blockIdx.x * 64;
    int bb = pix0 >> 12, n0 = pix0 & (N - 1);
    // stage x tile: 64 ch x 64 px (pitch 17 float4), coalesced
    {
        const float4* xs = (const float4*)(x + (size_t)bb * C * N + n0);
        float4* xd = (float4*)sX;
#pragma unroll
        for (int j = 0; j < 4; j++) {
            int id = t + 256 * j;                // 1024 float4
            int row = id >> 4, c4 = id & 15;
            xd[row * 17 + c4] = xs[(size_t)row * (N / 4) + c4];
        }
    }
    __syncthreads();

    // SE partial: ch = t&63, segment = t>>6 (16 px each), skewed reads
    {
        int ch = t & 63, seg = t >> 6;
        float s = 0.0f;
#pragma unroll
        for (int i = 0; i < 16; i++)
            s += sX[ch * XPITCH + seg * 16 + ((t + i) & 15)];
        spart[t] = s;
    }

    int quarter = t >> 6, px = t & 63;
    int pix = pix0 + px, n = n0 + px;

    if (quarter == 0) {
        // Q[8], K[8], V[0:4)
        float q[8], k[8], v[4];
#pragma unroll
        for (int o = 0; o < 8; o++) { q[o] = sbq[o]; k[o] = sbk[o]; }
#pragma unroll
        for (int i = 0; i < 4; i++) v[i] = sbv[i];
#pragma unroll 4
        for (int c4 = 0; c4 < 16; c4++) {
            int cb = c4 * 4;
            float x0 = sX[(cb + 0) * XPITCH + px];
            float x1 = sX[(cb + 1) * XPITCH + px];
            float x2 = sX[(cb + 2) * XPITCH + px];
            float x3 = sX[(cb + 3) * XPITCH + px];
#pragma unroll
            for (int o = 0; o < 8; o++) {
                float4 wq = sWq4[o * 16 + c4];
                q[o] = fmaf(wq.x, x0, fmaf(wq.y, x1, fmaf(wq.z, x2, fmaf(wq.w, x3, q[o]))));
                float4 wk = sWk4[o * 16 + c4];
                k[o] = fmaf(wk.x, x0, fmaf(wk.y, x1, fmaf(wk.z, x2, fmaf(wk.w, x3, k[o]))));
            }
#pragma unroll
            for (int i = 0; i < 4; i++) {
                float4 wv = sWv4[i * 16 + c4];
                v[i] = fmaf(wv.x, x0, fmaf(wv.y, x1, fmaf(wv.z, x2, fmaf(wv.w, x3, v[i]))));
            }
        }
        uint32_t w[4], u[4];
#pragma unroll
        for (int j = 0; j < 4; j++) {
            CVT2(w[j], q[2 * j] * QSCALE, q[2 * j + 1] * QSCALE);
            CVT2(u[j], k[2 * j], k[2 * j + 1]);
        }
        *(uint4*)(g_Qb + (size_t)pix * 8) = make_uint4(w[0], w[1], w[2], w[3]);
        *(uint4*)(g_Kb + (size_t)pix * 8) = make_uint4(u[0], u[1], u[2], u[3]);
#pragma unroll
        for (int i = 0; i < 4; i++)
            g_Vt[((size_t)bb * C + i) * N + n] = __float2bfloat16(v[i]);
    } else {
        // V[vbase : vbase+20)
        int vbase = quarter * 20 - 16;           // 4, 24, 44
        float a20[20];
#pragma unroll
        for (int i = 0; i < 20; i++) a20[i] = sbv[vbase + i];
#pragma unroll 4
        for (int c4 = 0; c4 < 16; c4++) {
            int cb = c4 * 4;
            float x0 = sX[(cb + 0) * XPITCH + px];
            float x1 = sX[(cb + 1) * XPITCH + px];
            float x2 = sX[(cb + 2) * XPITCH + px];
            float x3 = sX[(cb + 3) * XPITCH + px];
#pragma unroll
            for (int i = 0; i < 20; i++) {
                float4 wv = sWv4[(vbase + i) * 16 + c4];
                a20[i] = fmaf(wv.x, x0, fmaf(wv.y, x1, fmaf(wv.z, x2, fmaf(wv.w, x3, a20[i]))));
            }
        }
#pragma unroll
        for (int i = 0; i < 20; i++)
            g_Vt[((size_t)bb * C + vbase + i) * N + n] = __float2bfloat16(a20[i]);
    }

    __syncthreads();
    if (t < C)
        g_part[((size_t)bb * 64 + (blockIdx.x & 63)) * C + t] =
            (spart[t] + spart[t + 64]) + (spart[t + 128] + spart[t + 192]);
}

// ---------------------------------------------------------------------------
// Kernel 2: SE gate MLP. 4 blocks x 64 thr; sums per-CTA partials.
// ---------------------------------------------------------------------------
__global__ void gate_mlp_kernel(const float* __restrict__ W1, const float* __restrict__ b1,
                                const float* __restrict__ W2, const float* __restrict__ b2) {
    __shared__ float savg[C];
    __shared__ float shid[4];
    int b = blockIdx.x, t = threadIdx.x;   // 64 threads
    float s = 0.0f;
#pragma unroll 8
    for (int j = 0; j < 64; j++) s += g_part[((size_t)b * 64 + j) * C + t];
    savg[t] = s * (1.0f / (float)N);
    __syncthreads();
    if (t < 4) {
        float h = b1[t];
#pragma unroll
        for (int c = 0; c < C; c++) h = fmaf(W1[t * C + c], savg[c], h);
        shid[t] = fmaxf(h, 0.0f);
    }
    __syncthreads();
    float gg = b2[t];
#pragma unroll
    for (int j = 0; j < 4; j++) gg = fmaf(W2[t * 4 + j], shid[j], gg);
    g_gate[b * C + t] = 1.0f / (1.0f + __expf(-gg));
}

// ---------------------------------------------------------------------------
// Kernel 3: HMMA flash attention (R5 proven shape: 128 thr, 32 q/warp,
// split-K x2, ldmatrix frags, double-buffered cp.async).
// ---------------------------------------------------------------------------
#define OFF_GATE 0
#define OFF_K    256
#define OFF_V    (256 + 8192)
#define SMEM_ATTN (256 + 8192 + 4 * 17408)
#define VPITCH 272
#define REDP 66

__global__ void __launch_bounds__(128, 2) attn_kernel(float* __restrict__ out) {
    extern __shared__ char dsm[];
    uint32_t sb = smem_u32(dsm);
    int tid = threadIdx.x, w = tid >> 5, lane = tid & 31;
    int g = lane >> 2, t4 = lane & 3;
    int qg = w & 1, kh = w >> 1;
    int bb = blockIdx.x >> 6, qb = blockIdx.x & 63;
    int q0 = qb * 64 + qg * 32;

    if (tid < C) ((float*)(dsm + OFF_GATE))[tid] = g_gate[bb * C + tid];

    uint32_t qa[4];
    {
        const __nv_bfloat16* Qp = g_Qb + ((size_t)bb * N + q0) * 8 + t4 * 2;
#pragma unroll
        for (int r = 0; r < 4; r++)
            qa[r] = *(const uint32_t*)(Qp + (size_t)(r * 8 + g) * 8);
    }

    const char* kgb = (const char*)(g_Kb + (size_t)bb * N * 8);
    const char* vgb = (const char*)(g_Vt + (size_t)bb * C * N);

    uint32_t kfb = sb + OFF_K + kh * 4096 + (lane & 15) * 16;
    int vg2 = lane >> 3, vr = lane & 7;
    uint32_t vfb = sb + OFF_V + kh * 34816
                 + (uint32_t)(((vg2 >> 1) * 8 + vr) * VPITCH + (vg2 & 1) * 16);

#pragma unroll
    for (int h = 0; h < 2; h++) {
        int key0 = h * 2048;
        CP_ASYNC16(sb + OFF_K + h * 4096 + tid * 16, kgb + (size_t)key0 * 16 + tid * 16);
#pragma unroll
        for (int j = 0; j < 8; j++) {
            int id = tid + 128 * j, row = id >> 4, c16 = id & 15;
            CP_ASYNC16(sb + OFF_V + h * 34816 + row * VPITCH + c16 * 16,
                       vgb + ((size_t)row * N + key0) * 2 + c16 * 16);
        }
    }
    CP_COMMIT();

    float o[2][8][4] = {};
    float sums[4] = {0.f, 0.f, 0.f, 0.f};

#pragma unroll 1
    for (int kt = 0; kt < 16; kt++) {
        int buf = kt & 1;
        CP_WAIT0();
        __syncthreads();
        if (kt + 1 < 16) {
            int nb = (kt + 1) & 1;
#pragma unroll
            for (int h = 0; h < 2; h++) {
                int key0 = h * 2048 + (kt + 1) * 128;
                CP_ASYNC16(sb + OFF_K + (h * 2 + nb) * 2048 + tid * 16,
                           kgb + (size_t)key0 * 16 + tid * 16);
#pragma unroll
                for (int j = 0; j < 8; j++) {
                    int id = tid + 128 * j, row = id >> 4, c16 = id & 15;
                    CP_ASYNC16(sb + OFF_V + (h * 2 + nb) * 17408 + row * VPITCH + c16 * 16,
                               vgb + ((size_t)row * N + key0) * 2 + c16 * 16);
                }
            }
            CP_COMMIT();
        }
        uint32_t ka = kfb + buf * 2048;
        uint32_t va = vfb + buf * 17408;
#pragma unroll
        for (int nt2 = 0; nt2 < 8; nt2++) {
            uint32_t kk0, kk1;
            LDSM_X2(kk0, kk1, ka + nt2 * 256);
            uint32_t a[2][4];
#pragma unroll
            for (int blk = 0; blk < 2; blk++) {
                float c0 = 0, c1 = 0, c2 = 0, c3 = 0, c4 = 0, c5 = 0, c6 = 0, c7 = 0;
                mma_k8(c0, c1, c2, c3, qa[2 * blk], qa[2 * blk + 1], kk0);
                mma_k8(c4, c5, c6, c7, qa[2 * blk], qa[2 * blk + 1], kk1);
                float p0 = ex2f(c0), p1 = ex2f(c1), p2 = ex2f(c2), p3 = ex2f(c3);
                float p4 = ex2f(c4), p5 = ex2f(c5), p6 = ex2f(c6), p7 = ex2f(c7);
                sums[2 * blk]     += (p0 + p1) + (p4 + p5);
                sums[2 * blk + 1] += (p2 + p3) + (p6 + p7);
                CVT2(a[blk][0], p0, p1);
                CVT2(a[blk][1], p2, p3);
                CVT2(a[blk][2], p4, p5);
                CVT2(a[blk][3], p6, p7);
            }
#pragma unroll
            for (int cp = 0; cp < 4; cp++) {
                uint32_t b0, b1, b2, b3;
                LDSM_X4(b0, b1, b2, b3, va + cp * (16 * VPITCH) + nt2 * 32);
                mma_k16(o[0][2 * cp], a[0], b0, b1);
                mma_k16(o[1][2 * cp], a[1], b0, b1);
                mma_k16(o[0][2 * cp + 1], a[0], b2, b3);
                mma_k16(o[1][2 * cp + 1], a[1], b2, b3);
            }
        }
    }

#pragma unroll
    for (int j = 0; j < 4; j++) {
        sums[j] += __shfl_xor_sync(0xFFFFFFFFu, sums[j], 1);
        sums[j] += __shfl_xor_sync(0xFFFFFFFFu, sums[j], 2);
    }

    __syncthreads();
    float* red = (float*)(dsm + OFF_V) + qg * (32 * REDP);
    float* reds = (float*)(dsm + OFF_V + 2 * 32 * REDP * 4);   // [2][32]

    if (kh == 1) {
#pragma unroll
        for (int blk = 0; blk < 2; blk++)
#pragma unroll
            for (int ct = 0; ct < 8; ct++) {
#pragma unroll
                for (int i = 0; i < 4; i++) {
                    int row = blk * 16 + g + (i >> 1) * 8;
                    red[row * REDP + ct * 8 + t4 * 2 + (i & 1)] = o[blk][ct][i];
                }
            }
        if (t4 == 0) {
#pragma unroll
            for (int j = 0; j < 4; j++)
                reds[qg * 32 + ((j >> 1) * 16 + (j & 1) * 8) + g] = sums[j];
        }
    }
    __syncthreads();
    if (kh == 0) {
        float inv[4];
#pragma unroll
        for (int j = 0; j < 4; j++) {
            int row = (j >> 1) * 16 + (j & 1) * 8 + g;
            inv[j] = 1.0f / (sums[j] + reds[qg * 32 + row]);
        }
        const float* gt = (const float*)(dsm + OFF_GATE);
        float* outb = out + (size_t)bb * C * N;
#pragma unroll
        for (int blk = 0; blk < 2; blk++)
#pragma unroll
            for (int ct = 0; ct < 8; ct++) {
#pragma unroll
                for (int i = 0; i < 4; i++) {
                    int row = blk * 16 + g + (i >> 1) * 8;
                    int ch = ct * 8 + t4 * 2 + (i & 1);
                    float v = o[blk][ct][i] + red[row * REDP + ch];
                    outb[(size_t)ch * N + q0 + row] = v * inv[2 * blk + (i >> 1)] * gt[ch];
                }
            }
    }
}

// ---------------------------------------------------------------------------
extern "C" void kernel_launch(void* const* d_in, const int* in_sizes, int n_in,
                              void* d_out, int out_size) {
    const float* x  = (const float*)d_in[0];
    const float* Wq = (const float*)d_in[1];
    const float* bq = (const float*)d_in[2];
    const float* Wk = (const float*)d_in[3];
    const float* bk = (const float*)d_in[4];
    const float* Wv = (const float*)d_in[5];
    const float* bv = (const float*)d_in[6];
    const float* W1 = (const float*)d_in[7];
    const float* b1 = (const float*)d_in[8];
    const float* W2 = (const float*)d_in[9];
    const float* b2 = (const float*)d_in[10];
    float* out = (float*)d_out;

    static int smem_set = 0;
    if (!smem_set) {
        cudaFuncSetAttribute(attn_kernel, cudaFuncAttributeMaxDynamicSharedMemorySize, SMEM_ATTN);
        smem_set = 1;
    }

    qkv_kernel<<<256, 256>>>(x, Wq, bq, Wk, bk, Wv, bv);
    gate_mlp_kernel<<<B, C>>>(W1, b1, W2, b2);
    attn_kernel<<<B * 64, 128, SMEM_ATTN>>>(out);
}

// round 10
// speedup vs baseline: 1.6643x; 1.6643x over previous
#include <cuda_runtime.h>
#include <cuda_bf16.h>
#include <cstdint>
#include <math.h>

#define B 4
#define C 64
#define N 4096

// ---------------------------------------------------------------------------
// Scratch (device globals, allocation-free rule)
// ---------------------------------------------------------------------------
__device__ __align__(16) __nv_bfloat16 g_Qb[B * N * 8];   // [b][n][8], scaled 0.125*log2e
__device__ __align__(16) __nv_bfloat16 g_Kb[B * N * 8];   // [b][m][8]
__device__ __align__(16) __nv_bfloat16 g_Vt[B * C * N];   // [b][ch][m] transposed
__device__ float g_gate[B * C];
__device__ float g_part[B * 32 * C];                       // per-CTA channel sums

// ---------------------------------------------------------------------------
// Helpers
// ---------------------------------------------------------------------------
__device__ __forceinline__ uint32_t smem_u32(const void* p) {
    uint32_t a;
    asm("{ .reg .u64 t; cvta.to.shared.u64 t, %1; cvt.u32.u64 %0, t; }" : "=r"(a) : "l"(p));
    return a;
}
__device__ __forceinline__ float ex2f(float x) {
    float r;
    asm("ex2.approx.ftz.f32 %0, %1;" : "=f"(r) : "f"(x));
    return r;
}
__device__ __forceinline__ uint32_t swz128(uint32_t o) {   // apply to 16B-aligned offsets
    return o ^ ((o >> 3) & 0x70);
}
#define CVT2(r, a, b) \
    asm("cvt.rn.satfinite.bf16x2.f32 %0, %1, %2;" : "=r"(r) : "f"(b), "f"(a))
#define CP_ASYNC16(dst, src) \
    asm volatile("cp.async.cg.shared.global [%0], [%1], 16;" :: "r"(dst), "l"(src) : "memory")
#define CP_COMMIT() asm volatile("cp.async.commit_group;" ::: "memory")
#define CP_WAIT0()  asm volatile("cp.async.wait_group 0;" ::: "memory")

#define LDSM_X2(r0, r1, a) \
    asm volatile("ldmatrix.sync.aligned.m8n8.x2.shared.b16 {%0,%1}, [%2];" \
                 : "=r"(r0), "=r"(r1) : "r"(a))
#define LDSM_X4(r0, r1, r2, r3, a) \
    asm volatile("ldmatrix.sync.aligned.m8n8.x4.shared.b16 {%0,%1,%2,%3}, [%4];" \
                 : "=r"(r0), "=r"(r1), "=r"(r2), "=r"(r3) : "r"(a))

__device__ __forceinline__ void mma_k8(float& c0, float& c1, float& c2, float& c3,
                                       uint32_t a0, uint32_t a1, uint32_t b0) {
    asm volatile(
        "mma.sync.aligned.m16n8k8.row.col.f32.bf16.bf16.f32 "
        "{%0,%1,%2,%3}, {%4,%5}, {%6}, {%0,%1,%2,%3};"
        : "+f"(c0), "+f"(c1), "+f"(c2), "+f"(c3)
        : "r"(a0), "r"(a1), "r"(b0));
}
__device__ __forceinline__ void mma_k16(float* c, const uint32_t* a,
                                        uint32_t b0, uint32_t b1) {
    asm volatile(
        "mma.sync.aligned.m16n8k16.row.col.f32.bf16.bf16.f32 "
        "{%0,%1,%2,%3}, {%4,%5,%6,%7}, {%8,%9}, {%0,%1,%2,%3};"
        : "+f"(c[0]), "+f"(c[1]), "+f"(c[2]), "+f"(c[3])
        : "r"(a[0]), "r"(a[1]), "r"(a[2]), "r"(a[3]), "r"(b0), "r"(b1));
}

// exp(s/8) = 2^(s * 0.125*log2e); scale folded into Q
#define QSCALE (0.125f * 1.4426950408889634f)

// ---------------------------------------------------------------------------
// Kernel 1: QKV projections via HMMA + fused SE partial sums.
// 128 CTAs x 256 thr, 128 px/CTA. Weight block rows: [Wq(8); Wk(8); Wv(64)].
// Dynamic smem (61056 B):
//   QOFF_W     bf16 [80][64] swizzled, pitch 128B     (10240)
//   QOFF_BIAS  80 f32                                  (640 incl pad)
//   QOFF_XB    bf16 [128px][64ch] swizzled             (16384)
//   QOFF_UNION fp32 x [64ch][132]  (33792)  ->  later overlaid by
//              V-stage bf16 [64ch][136] (17408)
// ---------------------------------------------------------------------------
#define XP 132                               // fp32 stage pitch (128 px + 4 pad)
#define QOFF_W     0
#define QOFF_BIAS  10240
#define QOFF_XB    10880
#define QOFF_UNION 27264
#define QSMEM      (27264 + 64 * XP * 4)     // 61056

__global__ void __launch_bounds__(256) qkv_kernel(
    const float* __restrict__ x,
    const float* __restrict__ Wq, const float* __restrict__ bq,
    const float* __restrict__ Wk, const float* __restrict__ bk,
    const float* __restrict__ Wv, const float* __restrict__ bv) {
    extern __shared__ __align__(128) char sm[];
    uint32_t sb = smem_u32(sm);
    int t = threadIdx.x, lane = t & 31, w = t >> 5;
    int cta = blockIdx.x;
    int bb = cta >> 5;
    int n0 = (cta & 31) * 128;
    int pix0 = bb * N + n0;
    float* sXf = (float*)(sm + QOFF_UNION);          // [64][XP]
    float* sbias = (float*)(sm + QOFF_BIAS);

    // weights -> bf16 swizzled; biases
    for (int i = t; i < 1280; i += 256) {            // 80 rows x 16 float4
        int r = i >> 4, c4 = i & 15;
        const float* src = (r < 8) ? (Wq + r * 64)
                         : (r < 16) ? (Wk + (r - 8) * 64)
                                    : (Wv + (r - 16) * 64);
        float4 ww = ((const float4*)src)[c4];
        uint32_t p0, p1;
        CVT2(p0, ww.x, ww.y);
        CVT2(p1, ww.z, ww.w);
        uint32_t gr = swz128((uint32_t)(r * 128 + (c4 >> 1) * 16)) + (c4 & 1) * 8;
        *(uint32_t*)(sm + QOFF_W + gr) = p0;
        *(uint32_t*)(sm + QOFF_W + gr + 4) = p1;
    }
    if (t < 80) sbias[t] = (t < 8) ? bq[t] : (t < 16) ? bk[t - 8] : bv[t - 16];

    // stage x fp32: warp = ch0, lane = px-quad; 8 ch per thread, 128 px rows
    {
        int q4 = lane, ch0 = w;
#pragma unroll
        for (int j = 0; j < 8; j++) {
            int ch = ch0 + 8 * j;
            float4 v = *(const float4*)(x + (size_t)(bb * C + ch) * N + n0 + q4 * 4);
            *(float4*)(sXf + ch * XP + q4 * 4) = v;
        }
    }
    __syncthreads();

    // SE partial sums (t < 64): sum 128 px of channel t
    if (t < 64) {
        float s = 0.0f;
#pragma unroll 8
        for (int px = 0; px < 128; px++) s += sXf[t * XP + px];
        g_part[((size_t)bb * 32 + (cta & 31)) * C + t] = s;
    }

    // fp32 -> bf16 [px][ch] swizzled: thread (px = t&127, half = t>>7)
    {
        int px = t & 127, half = t >> 7;
#pragma unroll
        for (int s = 0; s < 4; s++) {
            int ch0 = half * 32 + s * 8;
            uint32_t u[4];
#pragma unroll
            for (int kk = 0; kk < 4; kk++) {
                float f0 = sXf[(ch0 + 2 * kk) * XP + px];
                float f1 = sXf[(ch0 + 2 * kk + 1) * XP + px];
                CVT2(u[kk], f0, f1);
            }
            uint32_t off = swz128((uint32_t)(px * 128 + half * 64 + s * 16));
            *(uint4*)(sm + QOFF_XB + off) = make_uint4(u[0], u[1], u[2], u[3]);
        }
    }
    __syncthreads();

    // MMA: warp w handles px rows [w*16, w*16+16), all 80 outputs
    int wpx = w * 16;
    float o10[10][4] = {};
    {
        uint32_t a_row = (uint32_t)((wpx + (lane & 15)) * 128 + (lane >> 4) * 16);
        uint32_t b_row = (uint32_t)((((lane >> 4) * 8) + (lane & 7)) * 128 + ((lane >> 3) & 1) * 16);
#pragma unroll
        for (int ks = 0; ks < 4; ks++) {
            uint32_t a[4];
            LDSM_X4(a[0], a[1], a[2], a[3], sb + QOFF_XB + swz128(a_row + ks * 32));
#pragma unroll
            for (int ntp = 0; ntp < 5; ntp++) {
                uint32_t b0, b1, b2, b3;
                LDSM_X4(b0, b1, b2, b3,
                        sb + QOFF_W + swz128(b_row + (uint32_t)(ntp * 16 * 128) + ks * 32));
                mma_k16(o10[2 * ntp], a, b0, b1);
                mma_k16(o10[2 * ntp + 1], a, b2, b3);
            }
        }
    }

    int g = lane >> 2, t4 = lane & 3;
    // Q (ntile 0): bias then QSCALE
    {
        float bA = sbias[2 * t4], bB = sbias[2 * t4 + 1];
        uint32_t r0, r1;
        CVT2(r0, (o10[0][0] + bA) * QSCALE, (o10[0][1] + bB) * QSCALE);
        CVT2(r1, (o10[0][2] + bA) * QSCALE, (o10[0][3] + bB) * QSCALE);
        *(uint32_t*)(g_Qb + (size_t)(pix0 + wpx + g) * 8 + 2 * t4) = r0;
        *(uint32_t*)(g_Qb + (size_t)(pix0 + wpx + 8 + g) * 8 + 2 * t4) = r1;
    }
    // K (ntile 1)
    {
        float bA = sbias[8 + 2 * t4], bB = sbias[8 + 2 * t4 + 1];
        uint32_t r0, r1;
        CVT2(r0, o10[1][0] + bA, o10[1][1] + bB);
        CVT2(r1, o10[1][2] + bA, o10[1][3] + bB);
        *(uint32_t*)(g_Kb + (size_t)(pix0 + wpx + g) * 8 + 2 * t4) = r0;
        *(uint32_t*)(g_Kb + (size_t)(pix0 + wpx + 8 + g) * 8 + 2 * t4) = r1;
    }
    // V (ntiles 2-9) -> smem transpose bounce (overlays sXf; all sXf reads done)
    __syncthreads();
    {
        __nv_bfloat16* sV = (__nv_bfloat16*)(sm + QOFF_UNION);   // [64][136]
#pragma unroll
        for (int nt = 2; nt < 10; nt++) {
            int ch = (nt - 2) * 8 + 2 * t4;
            float b0f = sbias[16 + ch], b1f = sbias[16 + ch + 1];
            sV[ch * 136 + wpx + g]           = __float2bfloat16(o10[nt][0] + b0f);
            sV[(ch + 1) * 136 + wpx + g]     = __float2bfloat16(o10[nt][1] + b1f);
            sV[ch * 136 + wpx + 8 + g]       = __float2bfloat16(o10[nt][2] + b0f);
            sV[(ch + 1) * 136 + wpx + 8 + g] = __float2bfloat16(o10[nt][3] + b1f);
        }
    }
    __syncthreads();
    // coalesced copy V-stage -> g_Vt
#pragma unroll
    for (int j = 0; j < 4; j++) {
        int i = t + 256 * j;
        int r = i >> 4, s = i & 15;
        uint4 v = *(const uint4*)(sm + QOFF_UNION + r * 272 + s * 16);
        *(uint4*)((char*)(g_Vt + (size_t)(bb * C + r) * N + n0 + s * 8)) = v;
    }
}

// ---------------------------------------------------------------------------
// Kernel 2: SE gate MLP. 4 blocks x 64 thr; sums per-CTA partials.
// ---------------------------------------------------------------------------
__global__ void gate_mlp_kernel(const float* __restrict__ W1, const float* __restrict__ b1,
                                const float* __restrict__ W2, const float* __restrict__ b2) {
    __shared__ float savg[C];
    __shared__ float shid[4];
    int b = blockIdx.x, t = threadIdx.x;   // 64 threads
    float s = 0.0f;
#pragma unroll 8
    for (int j = 0; j < 32; j++) s += g_part[((size_t)b * 32 + j) * C + t];
    savg[t] = s * (1.0f / (float)N);
    __syncthreads();
    if (t < 4) {
        float h = b1[t];
#pragma unroll
        for (int c = 0; c < C; c++) h = fmaf(W1[t * C + c], savg[c], h);
        shid[t] = fmaxf(h, 0.0f);
    }
    __syncthreads();
    float gg = b2[t];
#pragma unroll
    for (int j = 0; j < 4; j++) gg = fmaf(W2[t * 4 + j], shid[j], gg);
    g_gate[b * C + t] = 1.0f / (1.0f + __expf(-gg));
}

// ---------------------------------------------------------------------------
// Kernel 3: HMMA flash attention (R5 proven shape, verbatim).
// ---------------------------------------------------------------------------
#define OFF_GATE 0
#define OFF_K    256
#define OFF_V    (256 + 8192)
#define SMEM_ATTN (256 + 8192 + 4 * 17408)
#define VPITCH 272
#define REDP 66

__global__ void __launch_bounds__(128, 2) attn_kernel(float* __restrict__ out) {
    extern __shared__ char dsm[];
    uint32_t sb = smem_u32(dsm);
    int tid = threadIdx.x, w = tid >> 5, lane = tid & 31;
    int g = lane >> 2, t4 = lane & 3;
    int qg = w & 1, kh = w >> 1;
    int bb = blockIdx.x >> 6, qb = blockIdx.x & 63;
    int q0 = qb * 64 + qg * 32;

    if (tid < C) ((float*)(dsm + OFF_GATE))[tid] = g_gate[bb * C + tid];

    uint32_t qa[4];
    {
        const __nv_bfloat16* Qp = g_Qb + ((size_t)bb * N + q0) * 8 + t4 * 2;
#pragma unroll
        for (int r = 0; r < 4; r++)
            qa[r] = *(const uint32_t*)(Qp + (size_t)(r * 8 + g) * 8);
    }

    const char* kgb = (const char*)(g_Kb + (size_t)bb * N * 8);
    const char* vgb = (const char*)(g_Vt + (size_t)bb * C * N);

    uint32_t kfb = sb + OFF_K + kh * 4096 + (lane & 15) * 16;
    int vg2 = lane >> 3, vr = lane & 7;
    uint32_t vfb = sb + OFF_V + kh * 34816
                 + (uint32_t)(((vg2 >> 1) * 8 + vr) * VPITCH + (vg2 & 1) * 16);

#pragma unroll
    for (int h = 0; h < 2; h++) {
        int key0 = h * 2048;
        CP_ASYNC16(sb + OFF_K + h * 4096 + tid * 16, kgb + (size_t)key0 * 16 + tid * 16);
#pragma unroll
        for (int j = 0; j < 8; j++) {
            int id = tid + 128 * j, row = id >> 4, c16 = id & 15;
            CP_ASYNC16(sb + OFF_V + h * 34816 + row * VPITCH + c16 * 16,
                       vgb + ((size_t)row * N + key0) * 2 + c16 * 16);
        }
    }
    CP_COMMIT();

    float o[2][8][4] = {};
    float sums[4] = {0.f, 0.f, 0.f, 0.f};

#pragma unroll 1
    for (int kt = 0; kt < 16; kt++) {
        int buf = kt & 1;
        CP_WAIT0();
        __syncthreads();
        if (kt + 1 < 16) {
            int nb = (kt + 1) & 1;
#pragma unroll
            for (int h = 0; h < 2; h++) {
                int key0 = h * 2048 + (kt + 1) * 128;
                CP_ASYNC16(sb + OFF_K + (h * 2 + nb) * 2048 + tid * 16,
                           kgb + (size_t)key0 * 16 + tid * 16);
#pragma unroll
                for (int j = 0; j < 8; j++) {
                    int id = tid + 128 * j, row = id >> 4, c16 = id & 15;
                    CP_ASYNC16(sb + OFF_V + (h * 2 + nb) * 17408 + row * VPITCH + c16 * 16,
                               vgb + ((size_t)row * N + key0) * 2 + c16 * 16);
                }
            }
            CP_COMMIT();
        }
        uint32_t ka = kfb + buf * 2048;
        uint32_t va = vfb + buf * 17408;
#pragma unroll
        for (int nt2 = 0; nt2 < 8; nt2++) {
            uint32_t kk0, kk1;
            LDSM_X2(kk0, kk1, ka + nt2 * 256);
            uint32_t a[2][4];
#pragma unroll
            for (int blk = 0; blk < 2; blk++) {
                float c0 = 0, c1 = 0, c2 = 0, c3 = 0, c4 = 0, c5 = 0, c6 = 0, c7 = 0;
                mma_k8(c0, c1, c2, c3, qa[2 * blk], qa[2 * blk + 1], kk0);
                mma_k8(c4, c5, c6, c7, qa[2 * blk], qa[2 * blk + 1], kk1);
                float p0 = ex2f(c0), p1 = ex2f(c1), p2 = ex2f(c2), p3 = ex2f(c3);
                float p4 = ex2f(c4), p5 = ex2f(c5), p6 = ex2f(c6), p7 = ex2f(c7);
                sums[2 * blk]     += (p0 + p1) + (p4 + p5);
                sums[2 * blk + 1] += (p2 + p3) + (p6 + p7);
                CVT2(a[blk][0], p0, p1);
                CVT2(a[blk][1], p2, p3);
                CVT2(a[blk][2], p4, p5);
                CVT2(a[blk][3], p6, p7);
            }
#pragma unroll
            for (int cp = 0; cp < 4; cp++) {
                uint32_t b0, b1, b2, b3;
                LDSM_X4(b0, b1, b2, b3, va + cp * (16 * VPITCH) + nt2 * 32);
                mma_k16(o[0][2 * cp], a[0], b0, b1);
                mma_k16(o[1][2 * cp], a[1], b0, b1);
                mma_k16(o[0][2 * cp + 1], a[0], b2, b3);
                mma_k16(o[1][2 * cp + 1], a[1], b2, b3);
            }
        }
    }

#pragma unroll
    for (int j = 0; j < 4; j++) {
        sums[j] += __shfl_xor_sync(0xFFFFFFFFu, sums[j], 1);
        sums[j] += __shfl_xor_sync(0xFFFFFFFFu, sums[j], 2);
    }

    __syncthreads();
    float* red = (float*)(dsm + OFF_V) + qg * (32 * REDP);
    float* reds = (float*)(dsm + OFF_V + 2 * 32 * REDP * 4);   // [2][32]

    if (kh == 1) {
#pragma unroll
        for (int blk = 0; blk < 2; blk++)
#pragma unroll
            for (int ct = 0; ct < 8; ct++) {
#pragma unroll
                for (int i = 0; i < 4; i++) {
                    int row = blk * 16 + g + (i >> 1) * 8;
                    red[row * REDP + ct * 8 + t4 * 2 + (i & 1)] = o[blk][ct][i];
                }
            }
        if (t4 == 0) {
#pragma unroll
            for (int j = 0; j < 4; j++)
                reds[qg * 32 + ((j >> 1) * 16 + (j & 1) * 8) + g] = sums[j];
        }
    }
    __syncthreads();
    if (kh == 0) {
        float inv[4];
#pragma unroll
        for (int j = 0; j < 4; j++) {
            int row = (j >> 1) * 16 + (j & 1) * 8 + g;
            inv[j] = 1.0f / (sums[j] + reds[qg * 32 + row]);
        }
        const float* gt = (const float*)(dsm + OFF_GATE);
        float* outb = out + (size_t)bb * C * N;
#pragma unroll
        for (int blk = 0; blk < 2; blk++)
#pragma unroll
            for (int ct = 0; ct < 8; ct++) {
#pragma unroll
                for (int i = 0; i < 4; i++) {
                    int row = blk * 16 + g + (i >> 1) * 8;
                    int ch = ct * 8 + t4 * 2 + (i & 1);
                    float v = o[blk][ct][i] + red[row * REDP + ch];
                    outb[(size_t)ch * N + q0 + row] = v * inv[2 * blk + (i >> 1)] * gt[ch];
                }
            }
    }
}

// ---------------------------------------------------------------------------
extern "C" void kernel_launch(void* const* d_in, const int* in_sizes, int n_in,
                              void* d_out, int out_size) {
    const float* x  = (const float*)d_in[0];
    const float* Wq = (const float*)d_in[1];
    const float* bq = (const float*)d_in[2];
    const float* Wk = (const float*)d_in[3];
    const float* bk = (const float*)d_in[4];
    const float* Wv = (const float*)d_in[5];
    const float* bv = (const float*)d_in[6];
    const float* W1 = (const float*)d_in[7];
    const float* b1 = (const float*)d_in[8];
    const float* W2 = (const float*)d_in[9];
    const float* b2 = (const float*)d_in[10];
    float* out = (float*)d_out;

    cudaFuncSetAttribute(qkv_kernel, cudaFuncAttributeMaxDynamicSharedMemorySize, QSMEM);
    cudaFuncSetAttribute(attn_kernel, cudaFuncAttributeMaxDynamicSharedMemorySize, SMEM_ATTN);

    qkv_kernel<<<B * 32, 256, QSMEM>>>(x, Wq, bq, Wk, bk, Wv, bv);
    gate_mlp_kernel<<<B, C>>>(W1, b1, W2, b2);
    attn_kernel<<<B * 64, 128, SMEM_ATTN>>>(out);
}

// round 12
// speedup vs baseline: 1.6903x; 1.0156x over previous
#include <cuda_runtime.h>
#include <cuda_bf16.h>
#include <cuda_fp16.h>
#include <cstdint>
#include <math.h>

#define B 4
#define C 64
#define N 4096

// ---------------------------------------------------------------------------
// Scratch (device globals, allocation-free rule)
// ---------------------------------------------------------------------------
__device__ __align__(16) __nv_bfloat16 g_Qb[B * N * 8];   // [b][n][8], scaled 0.125*log2e
__device__ __align__(16) __nv_bfloat16 g_Kb[B * N * 8];   // [b][m][8]
__device__ __align__(16) __half        g_Vt[B * C * N];   // [b][ch][m] transposed, fp16
__device__ float g_gate[B * C];
__device__ float g_part[B * 32 * C];                       // per-CTA channel sums

// ---------------------------------------------------------------------------
// Helpers
// ---------------------------------------------------------------------------
__device__ __forceinline__ uint32_t smem_u32(const void* p) {
    uint32_t a;
    asm("{ .reg .u64 t; cvta.to.shared.u64 t, %1; cvt.u32.u64 %0, t; }" : "=r"(a) : "l"(p));
    return a;
}
__device__ __forceinline__ uint32_t swz128(uint32_t o) {   // apply to 16B-aligned offsets
    return o ^ ((o >> 3) & 0x70);
}
#define CVT2(r, a, b) \
    asm("cvt.rn.satfinite.bf16x2.f32 %0, %1, %2;" : "=r"(r) : "f"(b), "f"(a))
// pack two f32 -> f16x2 (lo, hi)
#define PACKH2(r, lo, hi) \
    asm("cvt.rn.f16x2.f32 %0, %1, %2;" : "=r"(r) : "f"(hi), "f"(lo))
// 2^x on both f16 halves (MUFU, 2 values per op)
#define EX2H2(r, s) \
    asm("ex2.approx.f16x2 %0, %1;" : "=r"(r) : "r"(s))
#define ONESH2 0x3C003C00u    // f16x2 {1.0, 1.0}

#define CP_ASYNC16(dst, src) \
    asm volatile("cp.async.cg.shared.global [%0], [%1], 16;" :: "r"(dst), "l"(src) : "memory")
#define CP_COMMIT() asm volatile("cp.async.commit_group;" ::: "memory")
#define CP_WAIT0()  asm volatile("cp.async.wait_group 0;" ::: "memory")

#define LDSM_X2(r0, r1, a) \
    asm volatile("ldmatrix.sync.aligned.m8n8.x2.shared.b16 {%0,%1}, [%2];" \
                 : "=r"(r0), "=r"(r1) : "r"(a))
#define LDSM_X4(r0, r1, r2, r3, a) \
    asm volatile("ldmatrix.sync.aligned.m8n8.x4.shared.b16 {%0,%1,%2,%3}, [%4];" \
                 : "=r"(r0), "=r"(r1), "=r"(r2), "=r"(r3) : "r"(a))

__device__ __forceinline__ void mma_k8(float& c0, float& c1, float& c2, float& c3,
                                       uint32_t a0, uint32_t a1, uint32_t b0) {
    asm volatile(
        "mma.sync.aligned.m16n8k8.row.col.f32.bf16.bf16.f32 "
        "{%0,%1,%2,%3}, {%4,%5}, {%6}, {%0,%1,%2,%3};"
        : "+f"(c0), "+f"(c1), "+f"(c2), "+f"(c3)
        : "r"(a0), "r"(a1), "r"(b0));
}
// bf16 k16 (qkv projections)
__device__ __forceinline__ void mma_k16(float* c, const uint32_t* a,
                                        uint32_t b0, uint32_t b1) {
    asm volatile(
        "mma.sync.aligned.m16n8k16.row.col.f32.bf16.bf16.f32 "
        "{%0,%1,%2,%3}, {%4,%5,%6,%7}, {%8,%9}, {%0,%1,%2,%3};"
        : "+f"(c[0]), "+f"(c[1]), "+f"(c[2]), "+f"(c[3])
        : "r"(a[0]), "r"(a[1]), "r"(a[2]), "r"(a[3]), "r"(b0), "r"(b1));
}
// f16 k16 (P*V and row-sum via ones)
__device__ __forceinline__ void mma_k16h(float* c, const uint32_t* a,
                                         uint32_t b0, uint32_t b1) {
    asm volatile(
        "mma.sync.aligned.m16n8k16.row.col.f32.f16.f16.f32 "
        "{%0,%1,%2,%3}, {%4,%5,%6,%7}, {%8,%9}, {%0,%1,%2,%3};"
        : "+f"(c[0]), "+f"(c[1]), "+f"(c[2]), "+f"(c[3])
        : "r"(a[0]), "r"(a[1]), "r"(a[2]), "r"(a[3]), "r"(b0), "r"(b1));
}

// exp(s/8) = 2^(s * 0.125*log2e); scale folded into Q
#define QSCALE (0.125f * 1.4426950408889634f)

// ---------------------------------------------------------------------------
// Kernel 1: QKV projections via HMMA + fused SE partial sums (R10 proven;
// only change: V stored as fp16).
// ---------------------------------------------------------------------------
#define XP 132
#define QOFF_W     0
#define QOFF_BIAS  10240
#define QOFF_XB    10880
#define QOFF_UNION 27264
#define QSMEM      (27264 + 64 * XP * 4)     // 61056

__global__ void __launch_bounds__(256) qkv_kernel(
    const float* __restrict__ x,
    const float* __restrict__ Wq, const float* __restrict__ bq,
    const float* __restrict__ Wk, const float* __restrict__ bk,
    const float* __restrict__ Wv, const float* __restrict__ bv) {
    extern __shared__ __align__(128) char sm[];
    uint32_t sb = smem_u32(sm);
    int t = threadIdx.x, lane = t & 31, w = t >> 5;
    int cta = blockIdx.x;
    int bb = cta >> 5;
    int n0 = (cta & 31) * 128;
    int pix0 = bb * N + n0;
    float* sXf = (float*)(sm + QOFF_UNION);          // [64][XP]
    float* sbias = (float*)(sm + QOFF_BIAS);

    for (int i = t; i < 1280; i += 256) {            // 80 rows x 16 float4
        int r = i >> 4, c4 = i & 15;
        const float* src = (r < 8) ? (Wq + r * 64)
                         : (r < 16) ? (Wk + (r - 8) * 64)
                                    : (Wv + (r - 16) * 64);
        float4 ww = ((const float4*)src)[c4];
        uint32_t p0, p1;
        CVT2(p0, ww.x, ww.y);
        CVT2(p1, ww.z, ww.w);
        uint32_t gr = swz128((uint32_t)(r * 128 + (c4 >> 1) * 16)) + (c4 & 1) * 8;
        *(uint32_t*)(sm + QOFF_W + gr) = p0;
        *(uint32_t*)(sm + QOFF_W + gr + 4) = p1;
    }
    if (t < 80) sbias[t] = (t < 8) ? bq[t] : (t < 16) ? bk[t - 8] : bv[t - 16];

    {
        int q4 = lane, ch0 = w;
#pragma unroll
        for (int j = 0; j < 8; j++) {
            int ch = ch0 + 8 * j;
            float4 v = *(const float4*)(x + (size_t)(bb * C + ch) * N + n0 + q4 * 4);
            *(float4*)(sXf + ch * XP + q4 * 4) = v;
        }
    }
    __syncthreads();

    if (t < 64) {
        float s = 0.0f;
#pragma unroll 8
        for (int px = 0; px < 128; px++) s += sXf[t * XP + px];
        g_part[((size_t)bb * 32 + (cta & 31)) * C + t] = s;
    }

    {
        int px = t & 127, half = t >> 7;
#pragma unroll
        for (int s = 0; s < 4; s++) {
            int ch0 = half * 32 + s * 8;
            uint32_t u[4];
#pragma unroll
            for (int kk = 0; kk < 4; kk++) {
                float f0 = sXf[(ch0 + 2 * kk) * XP + px];
                float f1 = sXf[(ch0 + 2 * kk + 1) * XP + px];
                CVT2(u[kk], f0, f1);
            }
            uint32_t off = swz128((uint32_t)(px * 128 + half * 64 + s * 16));
            *(uint4*)(sm + QOFF_XB + off) = make_uint4(u[0], u[1], u[2], u[3]);
        }
    }
    __syncthreads();

    int wpx = w * 16;
    float o10[10][4] = {};
    {
        uint32_t a_row = (uint32_t)((wpx + (lane & 15)) * 128 + (lane >> 4) * 16);
        uint32_t b_row = (uint32_t)((((lane >> 4) * 8) + (lane & 7)) * 128 + ((lane >> 3) & 1) * 16);
#pragma unroll
        for (int ks = 0; ks < 4; ks++) {
            uint32_t a[4];
            LDSM_X4(a[0], a[1], a[2], a[3], sb + QOFF_XB + swz128(a_row + ks * 32));
#pragma unroll
            for (int ntp = 0; ntp < 5; ntp++) {
                uint32_t b0, b1, b2, b3;
                LDSM_X4(b0, b1, b2, b3,
                        sb + QOFF_W + swz128(b_row + (uint32_t)(ntp * 16 * 128) + ks * 32));
                mma_k16(o10[2 * ntp], a, b0, b1);
                mma_k16(o10[2 * ntp + 1], a, b2, b3);
            }
        }
    }

    int g = lane >> 2, t4 = lane & 3;
    // Q (ntile 0)
    {
        float bA = sbias[2 * t4], bB = sbias[2 * t4 + 1];
        uint32_t r0, r1;
        CVT2(r0, (o10[0][0] + bA) * QSCALE, (o10[0][1] + bB) * QSCALE);
        CVT2(r1, (o10[0][2] + bA) * QSCALE, (o10[0][3] + bB) * QSCALE);
        *(uint32_t*)(g_Qb + (size_t)(pix0 + wpx + g) * 8 + 2 * t4) = r0;
        *(uint32_t*)(g_Qb + (size_t)(pix0 + wpx + 8 + g) * 8 + 2 * t4) = r1;
    }
    // K (ntile 1)
    {
        float bA = sbias[8 + 2 * t4], bB = sbias[8 + 2 * t4 + 1];
        uint32_t r0, r1;
        CVT2(r0, o10[1][0] + bA, o10[1][1] + bB);
        CVT2(r1, o10[1][2] + bA, o10[1][3] + bB);
        *(uint32_t*)(g_Kb + (size_t)(pix0 + wpx + g) * 8 + 2 * t4) = r0;
        *(uint32_t*)(g_Kb + (size_t)(pix0 + wpx + 8 + g) * 8 + 2 * t4) = r1;
    }
    // V (ntiles 2-9) -> fp16 smem transpose bounce
    __syncthreads();
    {
        __half* sV = (__half*)(sm + QOFF_UNION);   // [64][136]
#pragma unroll
        for (int nt = 2; nt < 10; nt++) {
            int ch = (nt - 2) * 8 + 2 * t4;
            float b0f = sbias[16 + ch], b1f = sbias[16 + ch + 1];
            sV[ch * 136 + wpx + g]           = __float2half(o10[nt][0] + b0f);
            sV[(ch + 1) * 136 + wpx + g]     = __float2half(o10[nt][1] + b1f);
            sV[ch * 136 + wpx + 8 + g]       = __float2half(o10[nt][2] + b0f);
            sV[(ch + 1) * 136 + wpx + 8 + g] = __float2half(o10[nt][3] + b1f);
        }
    }
    __syncthreads();
#pragma unroll
    for (int j = 0; j < 4; j++) {
        int i = t + 256 * j;
        int r = i >> 4, s = i & 15;
        uint4 v = *(const uint4*)(sm + QOFF_UNION + r * 272 + s * 16);
        *(uint4*)((char*)(g_Vt + (size_t)(bb * C + r) * N + n0 + s * 8)) = v;
    }
}

// ---------------------------------------------------------------------------
// Kernel 2: SE gate MLP. 4 blocks x 64 thr.
// ---------------------------------------------------------------------------
__global__ void gate_mlp_kernel(const float* __restrict__ W1, const float* __restrict__ b1,
                                const float* __restrict__ W2, const float* __restrict__ b2) {
    __shared__ float savg[C];
    __shared__ float shid[4];
    int b = blockIdx.x, t = threadIdx.x;
    float s = 0.0f;
#pragma unroll 8
    for (int j = 0; j < 32; j++) s += g_part[((size_t)b * 32 + j) * C + t];
    savg[t] = s * (1.0f / (float)N);
    __syncthreads();
    if (t < 4) {
        float h = b1[t];
#pragma unroll
        for (int c = 0; c < C; c++) h = fmaf(W1[t * C + c], savg[c], h);
        shid[t] = fmaxf(h, 0.0f);
    }
    __syncthreads();
    float gg = b2[t];
#pragma unroll
    for (int j = 0; j < 4; j++) gg = fmaf(W2[t * 4 + j], shid[j], gg);
    g_gate[b * C + t] = 1.0f / (1.0f + __expf(-gg));
}

// ---------------------------------------------------------------------------
// Kernel 3: HMMA flash attention. f16x2 exp path + ones-column row sums.
// ---------------------------------------------------------------------------
#define OFF_GATE 0
#define OFF_K    256
#define OFF_V    (256 + 8192)
#define SMEM_ATTN (256 + 8192 + 4 * 17408)
#define VPITCH 272
#define REDP 66

__global__ void __launch_bounds__(128, 2) attn_kernel(float* __restrict__ out) {
    extern __shared__ char dsm[];
    uint32_t sb = smem_u32(dsm);
    int tid = threadIdx.x, w = tid >> 5, lane = tid & 31;
    int g = lane >> 2, t4 = lane & 3;
    int qg = w & 1, kh = w >> 1;
    int bb = blockIdx.x >> 6, qb = blockIdx.x & 63;
    int q0 = qb * 64 + qg * 32;

    if (tid < C) ((float*)(dsm + OFF_GATE))[tid] = g_gate[bb * C + tid];

    uint32_t qa[4];
    {
        const __nv_bfloat16* Qp = g_Qb + ((size_t)bb * N + q0) * 8 + t4 * 2;
#pragma unroll
        for (int r = 0; r < 4; r++)
            qa[r] = *(const uint32_t*)(Qp + (size_t)(r * 8 + g) * 8);
    }

    const char* kgb = (const char*)(g_Kb + (size_t)bb * N * 8);
    const char* vgb = (const char*)(g_Vt + (size_t)bb * C * N);

    uint32_t kfb = sb + OFF_K + kh * 4096 + (lane & 15) * 16;
    int vg2 = lane >> 3, vr = lane & 7;
    uint32_t vfb = sb + OFF_V + kh * 34816
                 + (uint32_t)(((vg2 >> 1) * 8 + vr) * VPITCH + (vg2 & 1) * 16);

#pragma unroll
    for (int h = 0; h < 2; h++) {
        int key0 = h * 2048;
        CP_ASYNC16(sb + OFF_K + h * 4096 + tid * 16, kgb + (size_t)key0 * 16 + tid * 16);
#pragma unroll
        for (int j = 0; j < 8; j++) {
            int id = tid + 128 * j, row = id >> 4, c16 = id & 15;
            CP_ASYNC16(sb + OFF_V + h * 34816 + row * VPITCH + c16 * 16,
                       vgb + ((size_t)row * N + key0) * 2 + c16 * 16);
        }
    }
    CP_COMMIT();

    float o[2][8][4] = {};
    float sacc[2][4] = {};     // ones-column row sums: [blk][frag]

#pragma unroll 1
    for (int kt = 0; kt < 16; kt++) {
        int buf = kt & 1;
        CP_WAIT0();
        __syncthreads();
        if (kt + 1 < 16) {
            int nb = (kt + 1) & 1;
#pragma unroll
            for (int h = 0; h < 2; h++) {
                int key0 = h * 2048 + (kt + 1) * 128;
                CP_ASYNC16(sb + OFF_K + (h * 2 + nb) * 2048 + tid * 16,
                           kgb + (size_t)key0 * 16 + tid * 16);
#pragma unroll
                for (int j = 0; j < 8; j++) {
                    int id = tid + 128 * j, row = id >> 4, c16 = id & 15;
                    CP_ASYNC16(sb + OFF_V + (h * 2 + nb) * 17408 + row * VPITCH + c16 * 16,
                               vgb + ((size_t)row * N + key0) * 2 + c16 * 16);
                }
            }
            CP_COMMIT();
        }
        uint32_t ka = kfb + buf * 2048;
        uint32_t va = vfb + buf * 17408;
#pragma unroll
        for (int nt2 = 0; nt2 < 8; nt2++) {
            uint32_t kk0, kk1;
            LDSM_X2(kk0, kk1, ka + nt2 * 256);
            uint32_t a[2][4];
#pragma unroll
            for (int blk = 0; blk < 2; blk++) {
                float c0 = 0, c1 = 0, c2 = 0, c3 = 0, c4 = 0, c5 = 0, c6 = 0, c7 = 0;
                mma_k8(c0, c1, c2, c3, qa[2 * blk], qa[2 * blk + 1], kk0);
                mma_k8(c4, c5, c6, c7, qa[2 * blk], qa[2 * blk + 1], kk1);
                uint32_t s01, s23, s45, s67;
                PACKH2(s01, c0, c1);
                PACKH2(s23, c2, c3);
                PACKH2(s45, c4, c5);
                PACKH2(s67, c6, c7);
                EX2H2(a[blk][0], s01);     // P frag: row g,   k 2t4..2t4+1
                EX2H2(a[blk][1], s23);     //         row g+8
                EX2H2(a[blk][2], s45);     //         row g,   k 8+2t4..
                EX2H2(a[blk][3], s67);     //         row g+8
                mma_k16h(sacc[blk], a[blk], ONESH2, ONESH2);   // row sums
            }
#pragma unroll
            for (int cp = 0; cp < 4; cp++) {
                uint32_t b0, b1, b2, b3;
                LDSM_X4(b0, b1, b2, b3, va + cp * (16 * VPITCH) + nt2 * 32);
                mma_k16h(o[0][2 * cp], a[0], b0, b1);
                mma_k16h(o[1][2 * cp], a[1], b0, b1);
                mma_k16h(o[0][2 * cp + 1], a[0], b2, b3);
                mma_k16h(o[1][2 * cp + 1], a[1], b2, b3);
            }
        }
    }
    // sacc[blk][0] = full row sum for row blk*16+g; sacc[blk][2] for row blk*16+8+g
    // (every lane holds it; no shuffle reduction needed)

    __syncthreads();
    float* red = (float*)(dsm + OFF_V) + qg * (32 * REDP);
    float* reds = (float*)(dsm + OFF_V + 2 * 32 * REDP * 4);   // [2][32]

    if (kh == 1) {
#pragma unroll
        for (int blk = 0; blk < 2; blk++)
#pragma unroll
            for (int ct = 0; ct < 8; ct++) {
#pragma unroll
                for (int i = 0; i < 4; i++) {
                    int row = blk * 16 + g + (i >> 1) * 8;
                    red[row * REDP + ct * 8 + t4 * 2 + (i & 1)] = o[blk][ct][i];
                }
            }
        if (t4 == 0) {
#pragma unroll
            for (int blk = 0; blk < 2; blk++) {
                reds[qg * 32 + blk * 16 + g] = sacc[blk][0];
                reds[qg * 32 + blk * 16 + 8 + g] = sacc[blk][2];
            }
        }
    }
    __syncthreads();
    if (kh == 0) {
        float inv[2][2];
#pragma unroll
        for (int blk = 0; blk < 2; blk++) {
            inv[blk][0] = 1.0f / (sacc[blk][0] + reds[qg * 32 + blk * 16 + g]);
            inv[blk][1] = 1.0f / (sacc[blk][2] + reds[qg * 32 + blk * 16 + 8 + g]);
        }
        const float* gt = (const float*)(dsm + OFF_GATE);
        float* outb = out + (size_t)bb * C * N;
#pragma unroll
        for (int blk = 0; blk < 2; blk++)
#pragma unroll
            for (int ct = 0; ct < 8; ct++) {
#pragma unroll
                for (int i = 0; i < 4; i++) {
                    int row = blk * 16 + g + (i >> 1) * 8;
                    int ch = ct * 8 + t4 * 2 + (i & 1);
                    float v = o[blk][ct][i] + red[row * REDP + ch];
                    outb[(size_t)ch * N + q0 + row] = v * inv[blk][i >> 1] * gt[ch];
                }
            }
    }
}

// ---------------------------------------------------------------------------
extern "C" void kernel_launch(void* const* d_in, const int* in_sizes, int n_in,
                              void* d_out, int out_size) {
    const float* x  = (const float*)d_in[0];
    const float* Wq = (const float*)d_in[1];
    const float* bq = (const float*)d_in[2];
    const float* Wk = (const float*)d_in[3];
    const float* bk = (const float*)d_in[4];
    const float* Wv = (const float*)d_in[5];
    const float* bv = (const float*)d_in[6];
    const float* W1 = (const float*)d_in[7];
    const float* b1 = (const float*)d_in[8];
    const float* W2 = (const float*)d_in[9];
    const float* b2 = (const float*)d_in[10];
    float* out = (float*)d_out;

    cudaFuncSetAttribute(qkv_kernel, cudaFuncAttributeMaxDynamicSharedMemorySize, QSMEM);
    cudaFuncSetAttribute(attn_kernel, cudaFuncAttributeMaxDynamicSharedMemorySize, SMEM_ATTN);

    qkv_kernel<<<B * 32, 256, QSMEM>>>(x, Wq, bq, Wk, bk, Wv, bv);
    gate_mlp_kernel<<<B, C>>>(W1, b1, W2, b2);
    attn_kernel<<<B * 64, 128, SMEM_ATTN>>>(out);
}